// round 17
// baseline (speedup 1.0000x reference)
#include <cuda_runtime.h>
#include <cuda_bf16.h>
#include <cuda_fp16.h>
#include <math.h>
#include <stdint.h>

#define Bb   2
#define Ss   2048
#define Dd   2048
#define Hh   16
#define DHd  128
#define FFf  8192
#define ROWS 4096   // B*S

typedef __nv_bfloat16 bf16;

// ================= scratch (device globals) =================
__device__ bf16  g_h1h[(size_t)ROWS * Dd],  g_h1l[(size_t)ROWS * Dd];
__device__ __half g_h116[(size_t)ROWS * Dd];
__device__ bf16  g_wqkh[(size_t)2 * Dd * Dd], g_wqkl[(size_t)2 * Dd * Dd];
__device__ __half g_wvt16[(size_t)Dd * Dd];
__device__ __half g_wof16[(size_t)Dd * Dd];
__device__ __half g_fif16[(size_t)Dd * FFf];
__device__ __half g_fof16[(size_t)Dd * FFf];
__device__ bf16  g_qkh[(size_t)2 * ROWS * Dd], g_qkl[(size_t)2 * ROWS * Dd];
__device__ __half g_vt16[(size_t)Bb * Hh * DHd * Ss];
__device__ __half g_ah16[(size_t)Bb * Hh * Ss * Ss];
__device__ __half g_ctxh16[(size_t)ROWS * Dd];
__device__ float g_aproj[(size_t)ROWS * Dd];
__device__ float g_h2[(size_t)ROWS * Dd];
__device__ __half g_h216[(size_t)ROWS * Dd];
__device__ __half g_ffn16[(size_t)ROWS * FFf];
__device__ float g_sin[Ss * 64];
__device__ float g_cos[Ss * 64];

// ================= helpers =================
__device__ __forceinline__ uint32_t smem_u32(const void* p) {
    uint32_t a;
    asm("{ .reg .u64 t; cvta.to.shared.u64 t, %1; cvt.u32.u64 %0, t; }" : "=r"(a) : "l"(p));
    return a;
}
__device__ __forceinline__ void ldm4(uint32_t* r, uint32_t addr) {
    asm volatile("ldmatrix.sync.aligned.m8n8.x4.shared.b16 {%0,%1,%2,%3}, [%4];"
        : "=r"(r[0]), "=r"(r[1]), "=r"(r[2]), "=r"(r[3]) : "r"(addr));
}
__device__ __forceinline__ void mma_bf16(float* c, const uint32_t* a, const uint32_t* b) {
    asm volatile(
        "mma.sync.aligned.m16n8k16.row.col.f32.bf16.bf16.f32 "
        "{%0,%1,%2,%3}, {%4,%5,%6,%7}, {%8,%9}, {%0,%1,%2,%3};"
        : "+f"(c[0]), "+f"(c[1]), "+f"(c[2]), "+f"(c[3])
        : "r"(a[0]), "r"(a[1]), "r"(a[2]), "r"(a[3]), "r"(b[0]), "r"(b[1]));
}
__device__ __forceinline__ void mma_fp16(float* c, const uint32_t* a, const uint32_t* b) {
    asm volatile(
        "mma.sync.aligned.m16n8k16.row.col.f32.f16.f16.f32 "
        "{%0,%1,%2,%3}, {%4,%5,%6,%7}, {%8,%9}, {%0,%1,%2,%3};"
        : "+f"(c[0]), "+f"(c[1]), "+f"(c[2]), "+f"(c[3])
        : "r"(a[0]), "r"(a[1]), "r"(a[2]), "r"(a[3]), "r"(b[0]), "r"(b[1]));
}
__device__ __forceinline__ void cp16(uint32_t dst, const void* src) {
    asm volatile("cp.async.cg.shared.global [%0], [%1], 16;" :: "r"(dst), "l"(src));
}
__device__ __forceinline__ void cp_commit() { asm volatile("cp.async.commit_group;"); }
__device__ __forceinline__ void cp_wait1() { asm volatile("cp.async.wait_group 1;"); }
__device__ __forceinline__ void cp_wait0() { asm volatile("cp.async.wait_group 0;"); }

__device__ __forceinline__ void split2(float x, float y, bf16* ph, bf16* pl) {
    bf16 hx = __float2bfloat16_rn(x), hy = __float2bfloat16_rn(y);
    float fx = __bfloat162float(hx), fy = __bfloat162float(hy);
    __nv_bfloat162 h2; h2.x = hx; h2.y = hy;
    __nv_bfloat162 l2; l2.x = __float2bfloat16_rn(x - fx); l2.y = __float2bfloat16_rn(y - fy);
    *(__nv_bfloat162*)ph = h2;
    *(__nv_bfloat162*)pl = l2;
}

// ================= fused prep: 6 weight transposes + rope table =================
__device__ __forceinline__ void dev_tsplit(
    float (*t)[33], const float* __restrict__ in,
    bf16* __restrict__ oh, bf16* __restrict__ ol,
    int R, int Cc, int bxb, int byb)
{
    int bx = bxb * 32, by = byb * 64;
    int tx = threadIdx.x & 31, ty = threadIdx.x >> 5;
#pragma unroll
    for (int i = 0; i < 64; i += 8)
        t[ty + i][tx] = in[(size_t)(by + ty + i) * Cc + bx + tx];
    __syncthreads();
#pragma unroll
    for (int i = 0; i < 32; i += 8) {
        int r = ty + i;
        size_t o = (size_t)(bx + r) * R + by + 2 * tx;
        split2(t[2 * tx][r], t[2 * tx + 1][r], oh + o, ol + o);
    }
}
__device__ __forceinline__ void dev_tfp16(
    float (*t)[33], const float* __restrict__ in, __half* __restrict__ oh,
    int R, int Cc, int bxb, int byb)
{
    int bx = bxb * 32, by = byb * 64;
    int tx = threadIdx.x & 31, ty = threadIdx.x >> 5;
#pragma unroll
    for (int i = 0; i < 64; i += 8)
        t[ty + i][tx] = in[(size_t)(by + ty + i) * Cc + bx + tx];
    __syncthreads();
#pragma unroll
    for (int i = 0; i < 32; i += 8) {
        int r = ty + i;
        __half2 h2 = __floats2half2_rn(t[2 * tx][r], t[2 * tx + 1][r]);
        *(__half2*)(oh + (size_t)(bx + r) * R + by + 2 * tx) = h2;
    }
}

__global__ __launch_bounds__(256) void prep_kernel(
    const float* __restrict__ wq, const float* __restrict__ wk,
    const float* __restrict__ wv, const float* __restrict__ wo,
    const float* __restrict__ fiw, const float* __restrict__ fow,
    bf16* __restrict__ wqkh, bf16* __restrict__ wqkl,
    __half* __restrict__ wvt, __half* __restrict__ wof,
    __half* __restrict__ fif, __half* __restrict__ fof)
{
    __shared__ float t[64][33];
    int id = blockIdx.x;
    if (id < 2048) {
        dev_tsplit(t, wq, wqkh, wqkl, Dd, Dd, id & 63, id >> 6);
    } else if (id < 4096) {
        id -= 2048;
        dev_tsplit(t, wk, wqkh + (size_t)Dd * Dd, wqkl + (size_t)Dd * Dd, Dd, Dd, id & 63, id >> 6);
    } else if (id < 6144) {
        id -= 4096;
        dev_tfp16(t, wv, wvt, Dd, Dd, id & 63, id >> 6);
    } else if (id < 8192) {
        id -= 6144;
        dev_tfp16(t, wo, wof, Dd, Dd, id & 63, id >> 6);
    } else if (id < 16384) {
        id -= 8192;
        dev_tfp16(t, fiw, fif, Dd, FFf, id & 255, id >> 8);
    } else if (id < 24576) {
        id -= 16384;
        dev_tfp16(t, fow, fof, FFf, Dd, id & 63, id >> 6);
    } else {
        int tt = (id - 24576) * 256 + threadIdx.x;
        int p = tt >> 6, i = tt & 63;
        double inv = pow(10000.0, -((double)(2 * i)) / 128.0);
        float ang = (float)p * (float)inv;
        g_sin[tt] = (float)sin((double)ang);
        g_cos[tt] = (float)cos((double)ang);
    }
}

// ================= LayerNorm =================
__global__ __launch_bounds__(256) void ln_kernel(
    const float* __restrict__ x, const float* __restrict__ x2,
    const float* __restrict__ g, const float* __restrict__ bta,
    float* __restrict__ outf, bf16* __restrict__ outh, bf16* __restrict__ outl,
    __half* __restrict__ o16)
{
    __shared__ float red[256];
    int row = blockIdx.x, tid = threadIdx.x;
    size_t base = (size_t)row * Dd;
    float r[8];
    float s = 0.f;
#pragma unroll
    for (int t = 0; t < 8; t++) {
        int i = tid + t * 256;
        float v = x[base + i];
        if (x2) v += x2[base + i];
        r[t] = v; s += v;
    }
    red[tid] = s; __syncthreads();
    for (int o = 128; o > 0; o >>= 1) { if (tid < o) red[tid] += red[tid + o]; __syncthreads(); }
    float mean = red[0] * (1.0f / Dd);
    __syncthreads();
    float vs = 0.f;
#pragma unroll
    for (int t = 0; t < 8; t++) { float d = r[t] - mean; vs += d * d; }
    red[tid] = vs; __syncthreads();
    for (int o = 128; o > 0; o >>= 1) { if (tid < o) red[tid] += red[tid + o]; __syncthreads(); }
    float var = red[0] * (1.0f / Dd);
    float rs = rsqrtf(var + 1e-5f);
#pragma unroll
    for (int t = 0; t < 8; t++) {
        int i = tid + t * 256;
        float v = (r[t] - mean) * rs * g[i] + bta[i];
        if (outf) outf[base + i] = v;
        if (outh) {
            bf16 h = __float2bfloat16_rn(v);
            outh[base + i] = h;
            outl[base + i] = __float2bfloat16_rn(v - __bfloat162float(h));
        }
        if (o16) o16[base + i] = __float2half_rn(v);
    }
}

// ================= mixed-precision mma.sync GEMM =================
// MODE 0: bf16x3. MODE 2: fp16x1.
// flags: 1=bias 2=gelu 4=resid 8=qkv(rope+scatter) 16=score 32=ctx
//        64=bf16 hi/lo out 512=fp16 single out 1024=vtrans fp16 out
#define PPA 10240u            // A part bytes (128 rows * 80B)

template<int BN, int MODE, int MINCTAS, int NSTG>
__global__ __launch_bounds__(256, MINCTAS) void gemm_mp(
    const void* __restrict__ Ahv, const void* __restrict__ Alv,
    const void* __restrict__ Bhv, const void* __restrict__ Blv,
    const float* __restrict__ bias, const float* __restrict__ resid,
    float* __restrict__ Cf, void* __restrict__ Chv, void* __restrict__ Clv,
    const int* __restrict__ pid,
    int K, int lda, int ldb, int ldc, int flags)
{
    constexpr uint32_t PPB = (uint32_t)BN * 80u;
    constexpr uint32_t APARTS = (MODE == 2) ? 1u : 2u;
    constexpr uint32_t BPARTS = (MODE == 0) ? 2u : 1u;
    constexpr uint32_t STG = APARTS * PPA + BPARTS * PPB;
    constexpr int NFR = BN / 32;
    constexpr int NPAIR = NFR / 2;
    extern __shared__ char sm[];
    int bx = blockIdx.x, by = blockIdx.y, bz = blockIdx.z;
    const uint16_t* Ahp = (const uint16_t*)Ahv;
    const uint16_t* Alp = (const uint16_t*)Alv;
    const uint16_t* Bhp = (const uint16_t*)Bhv;
    const uint16_t* Blp = (const uint16_t*)Blv;
    float* Cfp = Cf;
    uint16_t* Chp = (uint16_t*)Chv;
    uint16_t* Clp = (uint16_t*)Clv;
    int Keff = K;
    const int tid = threadIdx.x, lane = tid & 31, warp = tid >> 5;
    if (flags & 16) {
        int b = bz >> 4, h = bz & 15;
        size_t ao = (size_t)b * Ss * Dd + h * DHd;
        Ahp += ao; Alp += ao; Bhp += ao; Blp += ao;
        Cfp += (size_t)bz * Ss * Ss;
        if (bx * BN > by * 128 + 127) {
            float4 z = make_float4(0.f, 0.f, 0.f, 0.f);
            float* tb = Cfp + (size_t)(by * 128) * ldc + bx * BN;
#pragma unroll
            for (int i = 0; i < (128 * BN / 4) / 256; i++) {
                int idx = tid + i * 256;
                int r = idx / (BN / 4), c4 = (idx % (BN / 4)) * 4;
                *(float4*)(tb + (size_t)r * ldc + c4) = z;
            }
            return;
        }
    }
    if (flags & 32) {
        bz = blockIdx.x;
        by = gridDim.y - 1 - blockIdx.y;
        bx = 0;
        int b = bz >> 4, h = bz & 15;
        size_t ao = (size_t)bz * Ss * Ss;
        size_t bo = (size_t)bz * DHd * Ss;
        Ahp += ao; Alp += ao; Bhp += bo; Blp += bo;
        size_t co = (size_t)b * Ss * Dd + h * DHd;
        Chp += co; Clp += co;
        Keff = (by + 1) * 128;
    }
    const int m0 = by * 128, n0 = bx * BN;
    const int wm = (warp >> 2) * 64, wn = (warp & 3) * (BN / 4);
    const uint32_t sbase = smem_u32(sm);

    float acc[4][NFR][4];
#pragma unroll
    for (int i = 0; i < 4; i++)
#pragma unroll
        for (int j = 0; j < NFR; j++)
#pragma unroll
            for (int e = 0; e < 4; e++) acc[i][j][e] = 0.f;

#define ISSUE_CHUNK(ST, K0) do { \
    uint32_t sb0 = sbase + (uint32_t)(ST) * STG; \
    _Pragma("unroll") \
    for (int i = 0; i < 2; i++) { \
        int idx = tid + i * 256; \
        int r = idx >> 2; int cc = idx & 3; \
        uint32_t d = sb0 + (uint32_t)r * 80u + (uint32_t)cc * 16u; \
        size_t sa = (size_t)(m0 + r) * lda + (K0) + cc * 8; \
        cp16(d, Ahp + sa); \
        if (MODE != 2) cp16(d + PPA, Alp + sa); \
    } \
    _Pragma("unroll") \
    for (int i = 0; i < BN / 64; i++) { \
        int idx = tid + i * 256; \
        int r = idx >> 2; int cc = idx & 3; \
        uint32_t d = sb0 + APARTS * PPA + (uint32_t)r * 80u + (uint32_t)cc * 16u; \
        size_t sb2 = (size_t)(n0 + r) * ldb + (K0) + cc * 8; \
        cp16(d, Bhp + sb2); \
        if (MODE == 0) cp16(d + PPB, Blp + sb2); \
    } \
    cp_commit(); \
} while(0)

    const uint32_t a_lane_off = (uint32_t)(wm + (lane & 15)) * 80u + (uint32_t)((lane >> 4) * 16);
    const uint32_t b_lane_off = (uint32_t)(wn + ((lane >> 4) * 8) + (lane & 7)) * 80u
                              + (uint32_t)(((lane >> 3) & 1) * 16);

    auto compute_chunk = [&](uint32_t boff) {
#pragma unroll
        for (int ks = 0; ks < 2; ks++) {
            uint32_t abase = sbase + boff + a_lane_off + (uint32_t)(ks * 32);
            uint32_t bbase = sbase + boff + APARTS * PPA + b_lane_off + (uint32_t)(ks * 32);
            if (MODE == 2) {
                // hoist ALL LDSM for this ks before any MMA (latency overlap)
                uint32_t ahi[4][4], bh4[NPAIR][4];
#pragma unroll
                for (int mti = 0; mti < 4; mti++)
                    ldm4(ahi[mti], abase + (uint32_t)(mti * 16) * 80u);
#pragma unroll
                for (int p = 0; p < NPAIR; p++)
                    ldm4(bh4[p], bbase + (uint32_t)(p * 16) * 80u);
#pragma unroll
                for (int p = 0; p < NPAIR; p++)
#pragma unroll
                    for (int mti = 0; mti < 4; mti++) {
                        mma_fp16(acc[mti][2 * p],     ahi[mti], bh4[p]);
                        mma_fp16(acc[mti][2 * p + 1], ahi[mti], bh4[p] + 2);
                    }
            } else {
                uint32_t ahi[4][4], alo[4][4];
#pragma unroll
                for (int mti = 0; mti < 4; mti++) {
                    ldm4(ahi[mti], abase + (uint32_t)(mti * 16) * 80u);
                    ldm4(alo[mti], abase + (uint32_t)(mti * 16) * 80u + PPA);
                }
#pragma unroll
                for (int p = 0; p < NPAIR; p++) {
                    uint32_t bh4[4], bl4[4];
                    ldm4(bh4, bbase + (uint32_t)(p * 16) * 80u);
                    ldm4(bl4, bbase + (uint32_t)(p * 16) * 80u + PPB);
#pragma unroll
                    for (int mti = 0; mti < 4; mti++) {
                        mma_bf16(acc[mti][2 * p],     ahi[mti], bh4);
                        mma_bf16(acc[mti][2 * p + 1], ahi[mti], bh4 + 2);
                    }
#pragma unroll
                    for (int mti = 0; mti < 4; mti++) {
                        mma_bf16(acc[mti][2 * p],     ahi[mti], bl4);
                        mma_bf16(acc[mti][2 * p + 1], ahi[mti], bl4 + 2);
                    }
#pragma unroll
                    for (int mti = 0; mti < 4; mti++) {
                        mma_bf16(acc[mti][2 * p],     alo[mti], bh4);
                        mma_bf16(acc[mti][2 * p + 1], alo[mti], bh4 + 2);
                    }
                }
            }
        }
    };

    const int nch = Keff / 32;
    if (NSTG == 2) {
        ISSUE_CHUNK(0, 0);
        for (int c = 0; c < nch; c++) {
            if (c + 1 < nch) { ISSUE_CHUNK((c + 1) & 1, (c + 1) * 32); cp_wait1(); }
            else cp_wait0();
            __syncthreads();
            compute_chunk((uint32_t)(c & 1) * STG);
            __syncthreads();
        }
    } else {
        // NSTG==4, nch always even: pairwise loop, ONE barrier per 2 chunks.
        // wait0 drains chunks c,c+1 (issued one pair ago); sync then guarantees
        // every warp consumed c-2,c-1, so their buffers are safe to re-issue.
        ISSUE_CHUNK(0, 0);
        if (nch > 1) ISSUE_CHUNK(1, 32);
        for (int c = 0; c < nch; c += 2) {
            cp_wait0();
            __syncthreads();
            if (c + 2 < nch) ISSUE_CHUNK((c + 2) % 4, (c + 2) * 32);
            if (c + 3 < nch) ISSUE_CHUNK((c + 3) % 4, (c + 3) * 32);
            compute_chunk((uint32_t)(c % 4) * STG);
            if (c + 1 < nch) compute_chunk((uint32_t)((c + 1) % 4) * STG);
        }
    }
#undef ISSUE_CHUNK

    // ---------------- vtrans epilogue: smem transpose -> vt16[bh][n][s] ----------------
    if (flags & 1024) {
        __syncthreads();
        __half* tile = (__half*)sm;
        const int PITCH = 136;
#pragma unroll
        for (int mti = 0; mti < 4; mti++)
#pragma unroll
            for (int ntj = 0; ntj < NFR; ntj++)
#pragma unroll
                for (int half = 0; half < 2; half++) {
                    int rowl = wm + mti * 16 + (lane >> 2) + half * 8;
                    int coll = wn + ntj * 8 + (lane & 3) * 2;
                    *(__half2*)&tile[rowl * PITCH + coll] =
                        __floats2half2_rn(acc[mti][ntj][half * 2], acc[mti][ntj][half * 2 + 1]);
                }
        __syncthreads();
        __half* dst = (__half*)Chp
            + ((size_t)((m0 >> 11) * Hh + bx) * DHd) * Ss + (m0 & 2047);
#pragma unroll
        for (int i = 0; i < 8; i++) {
            int linear = tid + i * 256;
            int n = linear & 127, s8 = (linear >> 7) * 8;
            __half tmp[8];
#pragma unroll
            for (int j = 0; j < 8; j++) tmp[j] = tile[(s8 + j) * PITCH + n];
            *(uint4*)(dst + (size_t)n * Ss + s8) = *(uint4*)tmp;
        }
        return;
    }

    // ---------------- standard epilogue ----------------
#pragma unroll
    for (int mti = 0; mti < 4; mti++) {
#pragma unroll
        for (int ntj = 0; ntj < NFR; ntj++) {
            int row = m0 + wm + mti * 16 + (lane >> 2);
            int col = n0 + wn + ntj * 8 + (lane & 3) * 2;
#pragma unroll
            for (int half = 0; half < 2; half++) {
                int rr = row + half * 8;
                float v0 = acc[mti][ntj][half * 2];
                float v1 = acc[mti][ntj][half * 2 + 1];
                if (flags & 1) { v0 += bias[col]; v1 += bias[col + 1]; }
                if (flags & 2) {
                    v0 = 0.5f * v0 * (1.0f + erff(v0 * 0.70710678118654752f));
                    v1 = 0.5f * v1 * (1.0f + erff(v1 * 0.70710678118654752f));
                }
                if (flags & 4) {
                    const float* rp = resid + (size_t)rr * ldc + col;
                    v0 += rp[0]; v1 += rp[1];
                }
                if (flags & 8) {
                    int sel = col >> 11, cl = col & 2047;
                    int b = rr >> 11, s = rr & 2047;
                    int pos = pid[b * Ss + s];
                    int i = (cl & 127) >> 1;
                    float sn = g_sin[pos * 64 + i], cs = g_cos[pos * 64 + i];
                    float r0 = v0 * cs - v1 * sn;
                    float r1 = v1 * cs + v0 * sn;
                    size_t o = (size_t)(sel * ROWS + rr) * Dd + cl;
                    split2(r0, r1, (bf16*)(Chp + o), (bf16*)(Clp + o));
                } else if (flags & 64) {
                    size_t o = (size_t)rr * ldc + col;
                    split2(v0, v1, (bf16*)(Chp + o), (bf16*)(Clp + o));
                } else if (flags & 512) {
                    size_t o = (size_t)rr * ldc + col;
                    *(__half2*)((__half*)Chp + o) = __floats2half2_rn(v0, v1);
                } else {
                    *(float2*)(Cfp + (size_t)rr * ldc + col) = make_float2(v0, v1);
                }
            }
        }
    }
}

// ================= row softmax (causal trunc, vectorized) + single fp16 out =================
__global__ __launch_bounds__(256) void softmax_kernel(
    float* __restrict__ attn, __half* __restrict__ ah)
{
    int rid = blockIdx.x;
    int qpos = rid & (Ss - 1);
    int L = qpos + 1;
    int Lpad = ((qpos >> 7) + 1) << 7;
    float* row = attn + (size_t)rid * Ss;
    __half* rh = ah + (size_t)rid * Ss;
    __shared__ float red[256];
    int tid = threadIdx.x;
    int base = tid * 8;
    float r[8];
    if (base < L) {
        float4 ra = *(const float4*)(row + base);
        float4 rb = *(const float4*)(row + base + 4);
        r[0] = ra.x; r[1] = ra.y; r[2] = ra.z; r[3] = ra.w;
        r[4] = rb.x; r[5] = rb.y; r[6] = rb.z; r[7] = rb.w;
    } else {
#pragma unroll
        for (int t = 0; t < 8; t++) r[t] = -3.4e38f;
    }
    float mx = -3.4e38f;
#pragma unroll
    for (int t = 0; t < 8; t++) {
        if (base + t >= L) r[t] = -3.4e38f;
        mx = fmaxf(mx, r[t]);
    }
    red[tid] = mx; __syncthreads();
    for (int o = 128; o > 0; o >>= 1) { if (tid < o) red[tid] = fmaxf(red[tid], red[tid + o]); __syncthreads(); }
    mx = red[0]; __syncthreads();
    float s = 0.f;
#pragma unroll
    for (int t = 0; t < 8; t++) {
        float e = (base + t < L) ? expf(r[t] - mx) : 0.0f;
        r[t] = e; s += e;
    }
    red[tid] = s; __syncthreads();
    for (int o = 128; o > 0; o >>= 1) { if (tid < o) red[tid] += red[tid + o]; __syncthreads(); }
    float inv = 1.0f / red[0];
#pragma unroll
    for (int t = 0; t < 8; t++) r[t] *= inv;
    if (base < Lpad) {
        *(float4*)(row + base)     = make_float4(r[0], r[1], r[2], r[3]);
        *(float4*)(row + base + 4) = make_float4(r[4], r[5], r[6], r[7]);
        __half2 hh[4];
#pragma unroll
        for (int j = 0; j < 4; j++)
            hh[j] = __floats2half2_rn(r[2 * j], r[2 * j + 1]);
        *(uint4*)(rh + base) = *(uint4*)hh;
    }
}

// ================= launch =================
extern "C" void kernel_launch(void* const* d_in, const int* in_sizes, int n_in,
                              void* d_out, int out_size)
{
    const float* hs   = (const float*)d_in[0];
    const int*   pid  = (const int*)  d_in[1];
    const float* wq   = (const float*)d_in[2];
    const float* wk   = (const float*)d_in[3];
    const float* wv   = (const float*)d_in[4];
    const float* wo   = (const float*)d_in[5];
    const float* ln1g = (const float*)d_in[6];
    const float* ln1b = (const float*)d_in[7];
    const float* ln2g = (const float*)d_in[8];
    const float* ln2b = (const float*)d_in[9];
    const float* fiw  = (const float*)d_in[10];
    const float* fib  = (const float*)d_in[11];
    const float* fow  = (const float*)d_in[12];
    const float* fob  = (const float*)d_in[13];

    float* out  = (float*)d_out;
    float* attn = out + (size_t)ROWS * Dd;

    float *aproj, *h2;
    bf16 *h1h, *h1l, *wqkh, *wqkl, *qkh, *qkl;
    __half *h116, *wvt, *wof, *fif, *fof, *vt16, *ah16;
    __half *ctxh16, *h216, *ffn16;
    cudaGetSymbolAddress((void**)&aproj,  g_aproj);
    cudaGetSymbolAddress((void**)&h2,     g_h2);
    cudaGetSymbolAddress((void**)&h1h,    g_h1h);
    cudaGetSymbolAddress((void**)&h1l,    g_h1l);
    cudaGetSymbolAddress((void**)&h116,   g_h116);
    cudaGetSymbolAddress((void**)&wqkh,   g_wqkh);
    cudaGetSymbolAddress((void**)&wqkl,   g_wqkl);
    cudaGetSymbolAddress((void**)&wvt,    g_wvt16);
    cudaGetSymbolAddress((void**)&wof,    g_wof16);
    cudaGetSymbolAddress((void**)&fif,    g_fif16);
    cudaGetSymbolAddress((void**)&fof,    g_fof16);
    cudaGetSymbolAddress((void**)&qkh,    g_qkh);
    cudaGetSymbolAddress((void**)&qkl,    g_qkl);
    cudaGetSymbolAddress((void**)&vt16,   g_vt16);
    cudaGetSymbolAddress((void**)&ah16,   g_ah16);
    cudaGetSymbolAddress((void**)&ctxh16, g_ctxh16);
    cudaGetSymbolAddress((void**)&h216,   g_h216);
    cudaGetSymbolAddress((void**)&ffn16,  g_ffn16);

    const uint32_t SMT128_0 = 2u * (2u * PPA + 2u * 128u * 80u);   // 81920, 2 CTAs
    const uint32_t SMT128_2 = 4u * (1u * PPA + 1u * 128u * 80u);   // 81920, 2 CTAs
    cudaFuncSetAttribute((const void*)gemm_mp<128, 0, 2, 2>, cudaFuncAttributeMaxDynamicSharedMemorySize, SMT128_0);
    cudaFuncSetAttribute((const void*)gemm_mp<128, 2, 2, 4>, cudaFuncAttributeMaxDynamicSharedMemorySize, SMT128_2);

    // fused prep: all weight transposes + rope table in one launch
    prep_kernel<<<25088, 256>>>(wq, wk, wv, wo, fiw, fow,
                                wqkh, wqkl, wvt, wof, fif, fof);

    // ln1 -> bf16 hi/lo (for qk) + fp16 single (for v)
    ln_kernel<<<ROWS, 256>>>(hs, nullptr, ln1g, ln1b, nullptr, h1h, h1l, h116);

    // qk projection (bf16x3, RoPE in epilogue); v projection (fp16x1, fused V^T epilogue)
    gemm_mp<128, 0, 2, 2><<<dim3(32, 32), 256, SMT128_0>>>(h1h, h1l, wqkh, wqkl,
        nullptr, nullptr, nullptr, qkh, qkl, pid, Dd, Dd, Dd, Dd, 8);
    gemm_mp<128, 2, 2, 4><<<dim3(16, 32), 256, SMT128_2>>>(h116, nullptr, wvt, nullptr,
        nullptr, nullptr, nullptr, vt16, nullptr, nullptr, Dd, Dd, Dd, Dd, 1024);

    // scores (bf16x3, causal, zero-fill) -> softmax (single fp16) -> ctx (fp16x1, single out)
    gemm_mp<128, 0, 2, 2><<<dim3(16, 16, Bb * Hh), 256, SMT128_0>>>(qkh, qkl,
        qkh + (size_t)ROWS * Dd, qkl + (size_t)ROWS * Dd,
        nullptr, nullptr, attn, nullptr, nullptr, nullptr, DHd, Dd, Dd, Ss, 16);
    softmax_kernel<<<Bb * Hh * Ss, 256>>>(attn, ah16);
    gemm_mp<128, 2, 2, 4><<<dim3(Bb * Hh, 16), 256, SMT128_2>>>(ah16, nullptr, vt16, nullptr,
        nullptr, nullptr, nullptr, ctxh16, nullptr, nullptr, Ss, Ss, Ss, Dd, 32 | 512);

    // output projection (fp16x1)
    gemm_mp<128, 2, 2, 4><<<dim3(16, 32), 256, SMT128_2>>>(ctxh16, nullptr, wof, nullptr,
        nullptr, nullptr, aproj, nullptr, nullptr, nullptr, Dd, Dd, Dd, Dd, 0);

    // ln2 -> fp32 + fp16 single
    ln_kernel<<<ROWS, 256>>>(hs, aproj, ln2g, ln2b, h2, nullptr, nullptr, h216);

    // FFN (fp16x1)
    gemm_mp<128, 2, 2, 4><<<dim3(64, 32), 256, SMT128_2>>>(h216, nullptr, fif, nullptr,
        fib, nullptr, nullptr, ffn16, nullptr, nullptr, Dd, Dd, Dd, FFf, 1 | 2 | 512);
    gemm_mp<128, 2, 2, 4><<<dim3(16, 32), 256, SMT128_2>>>(ffn16, nullptr, fof, nullptr,
        fob, h2, out, nullptr, nullptr, nullptr, FFf, FFf, FFf, Dd, 1 | 4);
}